// round 14
// baseline (speedup 1.0000x reference)
#include <cuda_runtime.h>
#include <cuda_fp16.h>
#include <cuda_bf16.h>
#include <math.h>

#define NN 50000
#define EE 800000
#define ETOT (EE + NN)
#define NEG_SLOPE 0.2f
#define EPS_DEN 1e-16f
#define FULLM 0xffffffffu

typedef unsigned long long ull;

// ---------------- scratch (static __device__, no allocs) ----------------
__device__ uint2 g_h1[NN * 32];       // layer1 features, fp16: 128 halves/node (4 per lane)
__device__ float g_asrc1[NN * 4];
__device__ float g_adst1[NN * 4];
__device__ float g_h2[NN * 2];
__device__ float g_asrc2[NN];
__device__ float g_adst2[NN];

__device__ int g_deg[NN];             // after k_offsets: includes self-loop
__device__ int g_rowstart[NN];
__device__ int g_cursor[NN];
__device__ int g_total;
__device__ int g_csrc[ETOT];          // CSR: src node per dst-grouped slot

// precomputed W1 fragments (hi/lo), layout [j(16)][ks(8)][lane(32)][2 words]
__device__ unsigned g_Bhi32[8192];
__device__ unsigned g_Blo32[8192];

// ---------------- CSR build ----------------
// edge_index is int32 on device (JAX x64-disabled demotes int64->int32)
__global__ void k_count(const int* __restrict__ ei) {
    int t = blockIdx.x * blockDim.x + threadIdx.x;
    if (t >= EE / 8) return;
    int4 a = reinterpret_cast<const int4*>(ei + EE)[2 * t];
    int4 b = reinterpret_cast<const int4*>(ei + EE)[2 * t + 1];
    atomicAdd(&g_deg[a.x], 1); atomicAdd(&g_deg[a.y], 1);
    atomicAdd(&g_deg[a.z], 1); atomicAdd(&g_deg[a.w], 1);
    atomicAdd(&g_deg[b.x], 1); atomicAdd(&g_deg[b.y], 1);
    atomicAdd(&g_deg[b.z], 1); atomicAdd(&g_deg[b.w], 1);
}

// row offsets: intra-block scan + ONE global atomic per block; folds +1 self-loop.
__global__ __launch_bounds__(256) void k_offsets() {
    __shared__ int wsum[8];
    __shared__ int sbase;
    int t = threadIdx.x;
    int n = blockIdx.x * 256 + t;
    int d = (n < NN) ? (g_deg[n] + 1) : 0;
    int lane = t & 31, wid = t >> 5;
    int incl = d;
#pragma unroll
    for (int off = 1; off < 32; off <<= 1) {
        int v = __shfl_up_sync(FULLM, incl, off);
        if (lane >= off) incl += v;
    }
    if (lane == 31) wsum[wid] = incl;
    __syncthreads();
    if (t == 0) {
        int run = 0;
#pragma unroll
        for (int w = 0; w < 8; w++) { int v = wsum[w]; wsum[w] = run; run += v; }
        sbase = atomicAdd(&g_total, run);
    }
    __syncthreads();
    if (n < NN) {
        int r = sbase + wsum[wid] + incl - d;
        g_deg[n] = d;
        g_rowstart[n] = r;
        g_cursor[n] = r;
    }
}

// scatter, 16 edges per thread (16 atomics in flight) + self-loop tail
__global__ void k_scatter(const int* __restrict__ ei) {
    int t = blockIdx.x * blockDim.x + threadIdx.x;
    if (t < EE / 16) {
        int4 s4[4], d4[4];
#pragma unroll
        for (int q = 0; q < 4; q++) {
            s4[q] = reinterpret_cast<const int4*>(ei)[4 * t + q];
            d4[q] = reinterpret_cast<const int4*>(ei + EE)[4 * t + q];
        }
        int p[16];
#pragma unroll
        for (int q = 0; q < 4; q++) {
            p[4 * q + 0] = atomicAdd(&g_cursor[d4[q].x], 1);
            p[4 * q + 1] = atomicAdd(&g_cursor[d4[q].y], 1);
            p[4 * q + 2] = atomicAdd(&g_cursor[d4[q].z], 1);
            p[4 * q + 3] = atomicAdd(&g_cursor[d4[q].w], 1);
        }
#pragma unroll
        for (int q = 0; q < 4; q++) {
            g_csrc[p[4 * q + 0]] = s4[q].x;
            g_csrc[p[4 * q + 1]] = s4[q].y;
            g_csrc[p[4 * q + 2]] = s4[q].z;
            g_csrc[p[4 * q + 3]] = s4[q].w;
        }
    } else {
        int n = t - EE / 16;
        if (n < NN) {
            int pos = atomicAdd(&g_cursor[n], 1);
            g_csrc[pos] = n;
        }
    }
}

// ---------------- one-time W1 fragment prep (hi/lo), word-level writes ----------------
__global__ void k_prepB(const float* __restrict__ W1) {
    int i = blockIdx.x * blockDim.x + threadIdx.x;   // 8192 words per array
    if (i >= 8192) return;
    int col = i & 127;
    int rest = i >> 7;              // 0..63
    int tg = rest & 3;
    int khalf = (rest >> 2) & 1;
    int ks = rest >> 3;             // 0..7
    int k0 = ks * 16 + khalf * 8 + tg * 2;
    float v0 = W1[k0 * 128 + col];        // coalesced across col
    float v1 = W1[(k0 + 1) * 128 + col];
    __nv_bfloat16 h0 = __float2bfloat16_rn(v0);
    __nv_bfloat16 h1 = __float2bfloat16_rn(v1);
    __nv_bfloat16 l0 = __float2bfloat16_rn(v0 - __bfloat162float(h0));
    __nv_bfloat16 l1 = __float2bfloat16_rn(v1 - __bfloat162float(h1));
    unsigned wh = (unsigned)*reinterpret_cast<unsigned short*>(&h0)
                | ((unsigned)*reinterpret_cast<unsigned short*>(&h1) << 16);
    unsigned wl = (unsigned)*reinterpret_cast<unsigned short*>(&l0)
                | ((unsigned)*reinterpret_cast<unsigned short*>(&l1) << 16);
    int j = col >> 3, g = col & 7;
    int widx = ((j * 8 + ks) * 32 + g * 4 + tg) * 2 + khalf;
    g_Bhi32[widx] = wh;
    g_Blo32[widx] = wl;
}

// ---------------- GEMM1 via mma.sync (bf16 hi/lo x3 passes) ----------------
// One CTA per 64-node tile, 8 warps; warp = (m16 slice mb 0..3, N-half jhalf).
// A frags in smem: [mb(4)][ks(8)][lane(32)][4 words] (16KB hi + 16KB lo).
// B frags read directly from precomputed GLOBAL arrays (L1-resident, every block
// reads the same 64KB). Epilogue stages h1 half2 via smem then coalesced STG.128.
#define GEMM_SMEM 32768
#define EPI_STRIDE 68

__device__ __forceinline__ void mma_bf16(float* c, uint4 a, uint2 b) {
    asm volatile(
        "mma.sync.aligned.m16n8k16.row.col.f32.bf16.bf16.f32 "
        "{%0,%1,%2,%3}, {%4,%5,%6,%7}, {%8,%9}, {%0,%1,%2,%3};"
        : "+f"(c[0]), "+f"(c[1]), "+f"(c[2]), "+f"(c[3])
        : "r"(a.x), "r"(a.y), "r"(a.z), "r"(a.w), "r"(b.x), "r"(b.y));
}

__global__ __launch_bounds__(256, 3) void k_gemm1(const float* __restrict__ x,
                                                  const float* __restrict__ att_s,
                                                  const float* __restrict__ att_d) {
    extern __shared__ char smem[];
    unsigned* sAhi = reinterpret_cast<unsigned*>(smem);
    unsigned* sAlo = reinterpret_cast<unsigned*>(smem + 16384);
    const int tid = threadIdx.x;
    const int n0 = blockIdx.x * 64;

    // ---- stage A (x rows -> bf16 hi/lo, fragment order), 64 rows ----
    for (int i = tid; i < 64 * 64; i += 256) {        // i = row*64 + kpair
        int row = i >> 6, kp = i & 63;
        int n = n0 + row;
        float2 v = make_float2(0.f, 0.f);
        if (n < NN) v = reinterpret_cast<const float2*>(x)[n * 64 + kp];
        __nv_bfloat16 hx = __float2bfloat16_rn(v.x);
        __nv_bfloat16 hy = __float2bfloat16_rn(v.y);
        __nv_bfloat16 lx = __float2bfloat16_rn(v.x - __bfloat162float(hx));
        __nv_bfloat16 ly = __float2bfloat16_rn(v.y - __bfloat162float(hy));
        __nv_bfloat162 hp = {hx, hy}, lp = {lx, ly};
        int mb = row >> 4, r = row & 15, g = r & 7, half = r >> 3;
        int ks = kp >> 3, kk = kp & 7;
        int tg = kk & 3, khalf = kk >> 2;
        int addr = ((mb * 8 + ks) * 32 + g * 4 + tg) * 4 + (khalf * 2 + half);
        sAhi[addr] = *reinterpret_cast<unsigned*>(&hp);
        sAlo[addr] = *reinterpret_cast<unsigned*>(&lp);
    }
    __syncthreads();

    // ---- mainloop: warp = (mb 0..3, jhalf 0..1); 3 passes x 8 ks x 8 jj ----
    const int wid = tid >> 5, lane = tid & 31;
    const int mb = wid & 3;
    const int jhalf = wid >> 2;
    const int jbase = jhalf * 8;
    const uint2* __restrict__ Bh = reinterpret_cast<const uint2*>(g_Bhi32);
    const uint2* __restrict__ Bl = reinterpret_cast<const uint2*>(g_Blo32);
    float c[8][4];
#pragma unroll
    for (int j = 0; j < 8; j++) {
        c[j][0] = 0.f; c[j][1] = 0.f; c[j][2] = 0.f; c[j][3] = 0.f;
    }
#pragma unroll 1
    for (int pass = 0; pass < 3; pass++) {
        const unsigned* sa = (pass < 2) ? sAhi : sAlo;
        const uint2* __restrict__ bg = (pass == 1) ? Bl : Bh;
#pragma unroll
        for (int ks = 0; ks < 8; ks++) {
            uint4 af = *reinterpret_cast<const uint4*>(&sa[((mb * 8 + ks) * 32 + lane) * 4]);
#pragma unroll
            for (int jj = 0; jj < 8; jj++) {
                int j = jbase + jj;
                uint2 bf = __ldg(&bg[(j * 8 + ks) * 32 + lane]);
                mma_bf16(c[jj], af, bf);
            }
        }
    }

    // ---- epilogue part 1: attention scalars (registers + shfl only) ----
    const int g = lane >> 2, tg = lane & 3;
    const int rowA = mb * 16 + g;
    const int rowB = rowA + 8;
    const int nA = n0 + rowA, nB = n0 + rowB;
    float psA[2] = {0, 0}, pdA[2] = {0, 0};
    float psB[2] = {0, 0}, pdB[2] = {0, 0};
#pragma unroll
    for (int jj = 0; jj < 8; jj++) {
        int j = jbase + jj;
        int col0 = 8 * j + 2 * tg;
        float s0 = att_s[col0], s1 = att_s[col0 + 1];
        float d0 = att_d[col0], d1 = att_d[col0 + 1];
        int hloc = jj >> 2;
        psA[hloc] += c[jj][0] * s0 + c[jj][1] * s1;
        pdA[hloc] += c[jj][0] * d0 + c[jj][1] * d1;
        psB[hloc] += c[jj][2] * s0 + c[jj][3] * s1;
        pdB[hloc] += c[jj][2] * d0 + c[jj][3] * d1;
    }
#pragma unroll
    for (int h = 0; h < 2; h++) {
#pragma unroll
        for (int off = 2; off > 0; off >>= 1) {
            psA[h] += __shfl_down_sync(FULLM, psA[h], off, 4);
            pdA[h] += __shfl_down_sync(FULLM, pdA[h], off, 4);
            psB[h] += __shfl_down_sync(FULLM, psB[h], off, 4);
            pdB[h] += __shfl_down_sync(FULLM, pdB[h], off, 4);
        }
    }
    if (tg == 0) {
#pragma unroll
        for (int h = 0; h < 2; h++) {
            int head = 2 * jhalf + h;
            if (nA < NN) { g_asrc1[nA * 4 + head] = psA[h]; g_adst1[nA * 4 + head] = pdA[h]; }
            if (nB < NN) { g_asrc1[nB * 4 + head] = psB[h]; g_adst1[nB * 4 + head] = pdB[h]; }
        }
    }

    // ---- epilogue part 2: h1 through smem (conflict-free STS, coalesced STG.128) ----
    __syncthreads();           // mainloop smem reads done; reuse A region for staging
    unsigned* sh = reinterpret_cast<unsigned*>(smem);   // [64 rows][EPI_STRIDE words]
#pragma unroll
    for (int jj = 0; jj < 8; jj++) {
        int j = jbase + jj;
        __half2 pA = __floats2half2_rn(c[jj][0], c[jj][1]);
        __half2 pB = __floats2half2_rn(c[jj][2], c[jj][3]);
        sh[rowA * EPI_STRIDE + 4 * j + tg] = *reinterpret_cast<unsigned*>(&pA);
        sh[rowB * EPI_STRIDE + 4 * j + tg] = *reinterpret_cast<unsigned*>(&pB);
    }
    __syncthreads();
    {
        uint4* h1u4 = reinterpret_cast<uint4*>(g_h1);
        for (int i = tid; i < 1024; i += 256) {       // 64 rows x 16 uint4
            int row = i >> 4, q = i & 15;
            int n = n0 + row;
            if (n < NN) {
                uint4 v = *reinterpret_cast<const uint4*>(&sh[row * EPI_STRIDE + 4 * q]);
                h1u4[n * 16 + q] = v;
            }
        }
    }
}

// ---------------- fused layer 1: softmax + aggregate + ELU + W2 proj ----------------
// one warp per destination node; fp16 h1 gathers (8B/lane/edge), unroll-8
__global__ __launch_bounds__(256) void k_layer1(const float* __restrict__ b1,
                                                const float* __restrict__ W2,
                                                const float* __restrict__ att_s2,
                                                const float* __restrict__ att_d2) {
    __shared__ int   ssrc[256];
    __shared__ float sex[256 * 4];
    int gt = blockIdx.x * blockDim.x + threadIdx.x;
    int n = gt >> 5;
    if (n >= NN) return;
    const int lane = gt & 31;
    const int head = lane >> 3;
    const int wslot = (threadIdx.x >> 5) * 32;

    const int beg = g_rowstart[n];
    const int end = beg + g_deg[n];
    const float4 adn = reinterpret_cast<const float4*>(g_adst1)[n];
    const uint2* __restrict__ h1v = g_h1;

    float acc0 = 0.0f, acc1 = 0.0f, acc2 = 0.0f, acc3 = 0.0f;
    float dx = 0.0f, dy = 0.0f, dz = 0.0f, dw = 0.0f;

    for (int c = beg; c < end; c += 32) {
        const int idx = c + lane;
        const int cnt = min(32, end - c);
        const int cnt8 = (cnt + 7) & ~7;
        __syncwarp(FULLM);
        {
            int s = g_csrc[min(idx, end - 1)];
            float4 as_ = reinterpret_cast<const float4*>(g_asrc1)[s];
            float v0 = as_.x + adn.x, v1 = as_.y + adn.y;
            float v2 = as_.z + adn.z, v3 = as_.w + adn.w;
            v0 = (v0 > 0.0f) ? v0 : NEG_SLOPE * v0;
            v1 = (v1 > 0.0f) ? v1 : NEG_SLOPE * v1;
            v2 = (v2 > 0.0f) ? v2 : NEG_SLOPE * v2;
            v3 = (v3 > 0.0f) ? v3 : NEG_SLOPE * v3;
            float e0 = expf(v0), e1 = expf(v1), e2 = expf(v2), e3 = expf(v3);
            if (idx >= end) { e0 = e1 = e2 = e3 = 0.0f; }
            dx += e0; dy += e1; dz += e2; dw += e3;
            ssrc[wslot + lane] = s;
            float* p = &sex[(wslot + lane) * 4];
            p[0] = e0; p[1] = e1; p[2] = e2; p[3] = e3;
        }
        __syncwarp(FULLM);
        for (int j = 0; j < cnt8; j += 8) {
            uint2 u[8];
#pragma unroll
            for (int i = 0; i < 8; i++) {
                int s = ssrc[wslot + j + i];
                u[i] = h1v[s * 32 + lane];
            }
#pragma unroll
            for (int i = 0; i < 8; i++) {
                float ex = sex[(wslot + j + i) * 4 + head];
                float2 a = __half22float2(*reinterpret_cast<__half2*>(&u[i].x));
                float2 b = __half22float2(*reinterpret_cast<__half2*>(&u[i].y));
                acc0 = fmaf(ex, a.x, acc0);
                acc1 = fmaf(ex, a.y, acc1);
                acc2 = fmaf(ex, b.x, acc2);
                acc3 = fmaf(ex, b.y, acc3);
            }
        }
    }
#pragma unroll
    for (int off = 16; off > 0; off >>= 1) {
        dx += __shfl_xor_sync(FULLM, dx, off);
        dy += __shfl_xor_sync(FULLM, dy, off);
        dz += __shfl_xor_sync(FULLM, dz, off);
        dw += __shfl_xor_sync(FULLM, dw, off);
    }
    float denh = (head == 0) ? dx : (head == 1) ? dy : (head == 2) ? dz : dw;
    float r = 1.0f / (denh + EPS_DEN);

    float av[4] = {acc0, acc1, acc2, acc3};
    float p0 = 0.0f, p1 = 0.0f;
#pragma unroll
    for (int m = 0; m < 4; m++) {
        int k = 4 * lane + m;
        float v = av[m] * r + b1[k];
        float ev = (v > 0.0f) ? v : expm1f(v);   // ELU
        p0 = fmaf(ev, W2[k * 2 + 0], p0);
        p1 = fmaf(ev, W2[k * 2 + 1], p1);
    }
#pragma unroll
    for (int off = 16; off > 0; off >>= 1) {
        p0 += __shfl_down_sync(FULLM, p0, off);
        p1 += __shfl_down_sync(FULLM, p1, off);
    }
    if (lane == 0) {
        g_h2[n * 2 + 0] = p0;
        g_h2[n * 2 + 1] = p1;
        g_asrc2[n] = p0 * att_s2[0] + p1 * att_s2[1];
        g_adst2[n] = p0 * att_d2[0] + p1 * att_d2[1];
    }
}

// ---------------- fused layer 2: softmax + aggregate + log_softmax ----------------
__global__ __launch_bounds__(256) void k_layer2(const float* __restrict__ b2,
                                                float* __restrict__ out) {
    int gt = blockIdx.x * blockDim.x + threadIdx.x;
    int n = gt >> 3;
    if (n >= NN) return;
    const int lane = gt & 7;

    const int beg = g_rowstart[n];
    const int end = beg + g_deg[n];
    const float adn = g_adst2[n];

    float den = 0.0f, o0 = 0.0f, o1 = 0.0f;
    for (int idx = beg + lane; idx < end; idx += 8) {
        int s = g_csrc[idx];
        float v = g_asrc2[s] + adn;
        v = (v > 0.0f) ? v : NEG_SLOPE * v;
        float ex = expf(v);
        float2 h = reinterpret_cast<const float2*>(g_h2)[s];
        den += ex;
        o0 = fmaf(ex, h.x, o0);
        o1 = fmaf(ex, h.y, o1);
    }
#pragma unroll
    for (int off = 4; off > 0; off >>= 1) {
        den += __shfl_down_sync(FULLM, den, off, 8);
        o0  += __shfl_down_sync(FULLM, o0, off, 8);
        o1  += __shfl_down_sync(FULLM, o1, off, 8);
    }
    if (lane == 0) {
        float r = 1.0f / (den + EPS_DEN);
        float a = o0 * r + b2[0];
        float b = o1 * r + b2[1];
        float m = fmaxf(a, b);
        float l = m + logf(expf(a - m) + expf(b - m));
        out[n * 2 + 0] = a - l;
        out[n * 2 + 1] = b - l;
    }
}

// ---------------- launch ----------------
extern "C" void kernel_launch(void* const* d_in, const int* in_sizes, int n_in,
                              void* d_out, int out_size) {
    const float* x    = (const float*)d_in[0];
    const int*   ei   = (const int*)d_in[1];
    const float* W1   = (const float*)d_in[2];
    const float* as1  = (const float*)d_in[3];
    const float* ad1  = (const float*)d_in[4];
    const float* b1   = (const float*)d_in[5];
    const float* W2   = (const float*)d_in[6];
    const float* as2  = (const float*)d_in[7];
    const float* ad2  = (const float*)d_in[8];
    const float* b2   = (const float*)d_in[9];
    float* out = (float*)d_out;

    (void)in_sizes; (void)n_in; (void)out_size;

    static cudaStream_t s_side = nullptr;
    static cudaEvent_t  s_evFork = nullptr, s_evJoin = nullptr;
    static void *p_deg = nullptr, *p_total = nullptr;
    if (s_side == nullptr) {
        cudaStreamCreateWithFlags(&s_side, cudaStreamNonBlocking);
        cudaEventCreateWithFlags(&s_evFork, cudaEventDisableTiming);
        cudaEventCreateWithFlags(&s_evJoin, cudaEventDisableTiming);
        cudaGetSymbolAddress(&p_deg, g_deg);
        cudaGetSymbolAddress(&p_total, g_total);
        cudaFuncSetAttribute(k_gemm1, cudaFuncAttributeMaxDynamicSharedMemorySize, GEMM_SMEM);
    }

    // fork: CSR build on side stream, prepB+gemm1 on main (disjoint state).
    // API-call order puts k_gemm1 at capture node #6 so ncu (-s 5 -c 1) profiles it.
    cudaEventRecord(s_evFork, 0);
    cudaStreamWaitEvent(s_side, s_evFork, 0);

    cudaMemsetAsync(p_deg, 0, NN * sizeof(int), s_side);         // 1
    cudaMemsetAsync(p_total, 0, sizeof(int), s_side);            // 2
    k_count<<<(EE / 8 + 255) / 256, 256, 0, s_side>>>(ei);       // 3
    k_offsets<<<(NN + 255) / 256, 256, 0, s_side>>>();           // 4

    k_prepB<<<32, 256>>>(W1);                                    // 5 (main)
    k_gemm1<<<(NN + 63) / 64, 256, GEMM_SMEM>>>(x, as1, ad1);    // 6 (main) <- profiled

    k_scatter<<<(EE / 16 + NN + 255) / 256, 256, 0, s_side>>>(ei); // 7 (side)
    cudaEventRecord(s_evJoin, s_side);

    // join: layer kernels need both CSR and gemm outputs
    cudaStreamWaitEvent(0, s_evJoin, 0);

    {
        long long tot = (long long)NN * 32;
        k_layer1<<<(int)((tot + 255) / 256), 256>>>(b1, W2, as2, ad2);  // 8
    }
    {
        long long tot = (long long)NN * 8;
        k_layer2<<<(int)((tot + 255) / 256), 256>>>(b2, out);           // 9
    }
}

// round 15
// speedup vs baseline: 1.1229x; 1.1229x over previous
#include <cuda_runtime.h>
#include <cuda_fp16.h>
#include <cuda_bf16.h>
#include <math.h>

#define NN 50000
#define EE 800000
#define ETOT (EE + NN)
#define NEG_SLOPE 0.2f
#define EPS_DEN 1e-16f
#define FULLM 0xffffffffu

typedef unsigned long long ull;

// ---------------- scratch (static __device__, no allocs) ----------------
__device__ uint2 g_h1[NN * 32];       // layer1 features, fp16: 128 halves/node (4 per lane)
__device__ float g_asrc1[NN * 4];
__device__ float g_adst1[NN * 4];
__device__ float g_h2[NN * 2];
__device__ float g_asrc2[NN];
__device__ float g_adst2[NN];

__device__ int g_deg[NN];             // after k_offsets: includes self-loop
__device__ int g_rowstart[NN];
__device__ int g_cursor[NN];
__device__ int g_total;
__device__ int g_csrc[ETOT];          // CSR: src node per dst-grouped slot

// precomputed W1 fragments (bf16 hi only), layout [j(16)][ks(8)][lane(32)][2 words]
__device__ unsigned g_Bhi32[8192];

// ---------------- CSR build ----------------
// edge_index is int32 on device (JAX x64-disabled demotes int64->int32)
__global__ void k_count(const int* __restrict__ ei) {
    int t = blockIdx.x * blockDim.x + threadIdx.x;
    if (t >= EE / 8) return;
    int4 a = reinterpret_cast<const int4*>(ei + EE)[2 * t];
    int4 b = reinterpret_cast<const int4*>(ei + EE)[2 * t + 1];
    atomicAdd(&g_deg[a.x], 1); atomicAdd(&g_deg[a.y], 1);
    atomicAdd(&g_deg[a.z], 1); atomicAdd(&g_deg[a.w], 1);
    atomicAdd(&g_deg[b.x], 1); atomicAdd(&g_deg[b.y], 1);
    atomicAdd(&g_deg[b.z], 1); atomicAdd(&g_deg[b.w], 1);
}

// row offsets: intra-block scan + ONE global atomic per block; folds +1 self-loop.
__global__ __launch_bounds__(256) void k_offsets() {
    __shared__ int wsum[8];
    __shared__ int sbase;
    int t = threadIdx.x;
    int n = blockIdx.x * 256 + t;
    int d = (n < NN) ? (g_deg[n] + 1) : 0;
    int lane = t & 31, wid = t >> 5;
    int incl = d;
#pragma unroll
    for (int off = 1; off < 32; off <<= 1) {
        int v = __shfl_up_sync(FULLM, incl, off);
        if (lane >= off) incl += v;
    }
    if (lane == 31) wsum[wid] = incl;
    __syncthreads();
    if (t == 0) {
        int run = 0;
#pragma unroll
        for (int w = 0; w < 8; w++) { int v = wsum[w]; wsum[w] = run; run += v; }
        sbase = atomicAdd(&g_total, run);
    }
    __syncthreads();
    if (n < NN) {
        int r = sbase + wsum[wid] + incl - d;
        g_deg[n] = d;
        g_rowstart[n] = r;
        g_cursor[n] = r;
    }
}

// scatter, 8 edges per thread (8 atomics in flight) + self-loop tail
__global__ void k_scatter(const int* __restrict__ ei) {
    int t = blockIdx.x * blockDim.x + threadIdx.x;
    if (t < EE / 8) {
        int4 sa = reinterpret_cast<const int4*>(ei)[2 * t];
        int4 sb = reinterpret_cast<const int4*>(ei)[2 * t + 1];
        int4 da = reinterpret_cast<const int4*>(ei + EE)[2 * t];
        int4 db = reinterpret_cast<const int4*>(ei + EE)[2 * t + 1];
        int p0 = atomicAdd(&g_cursor[da.x], 1);
        int p1 = atomicAdd(&g_cursor[da.y], 1);
        int p2 = atomicAdd(&g_cursor[da.z], 1);
        int p3 = atomicAdd(&g_cursor[da.w], 1);
        int p4 = atomicAdd(&g_cursor[db.x], 1);
        int p5 = atomicAdd(&g_cursor[db.y], 1);
        int p6 = atomicAdd(&g_cursor[db.z], 1);
        int p7 = atomicAdd(&g_cursor[db.w], 1);
        g_csrc[p0] = sa.x; g_csrc[p1] = sa.y; g_csrc[p2] = sa.z; g_csrc[p3] = sa.w;
        g_csrc[p4] = sb.x; g_csrc[p5] = sb.y; g_csrc[p6] = sb.z; g_csrc[p7] = sb.w;
    } else {
        int n = t - EE / 8;
        if (n < NN) {
            int pos = atomicAdd(&g_cursor[n], 1);
            g_csrc[pos] = n;
        }
    }
}

// ---------------- one-time W1 fragment prep (bf16 hi only) ----------------
__global__ void k_prepB(const float* __restrict__ W1) {
    int i = blockIdx.x * blockDim.x + threadIdx.x;   // 8192 words
    if (i >= 8192) return;
    int col = i & 127;
    int rest = i >> 7;              // 0..63
    int tg = rest & 3;
    int khalf = (rest >> 2) & 1;
    int ks = rest >> 3;             // 0..7
    int k0 = ks * 16 + khalf * 8 + tg * 2;
    float v0 = W1[k0 * 128 + col];        // coalesced across col
    float v1 = W1[(k0 + 1) * 128 + col];
    __nv_bfloat16 h0 = __float2bfloat16_rn(v0);
    __nv_bfloat16 h1 = __float2bfloat16_rn(v1);
    unsigned wh = (unsigned)*reinterpret_cast<unsigned short*>(&h0)
                | ((unsigned)*reinterpret_cast<unsigned short*>(&h1) << 16);
    int j = col >> 3, g = col & 7;
    int widx = ((j * 8 + ks) * 32 + g * 4 + tg) * 2 + khalf;
    g_Bhi32[widx] = wh;
}

// ---------------- GEMM1 via mma.sync (2-pass: Ahi*B + Alo*B, bf16 B) ----------------
// One CTA per 64-node tile, 8 warps; warp = (m16 slice mb 0..3, N-half jhalf).
// smem: B frags 32KB (copied once, coalesced) + A hi 16KB + A lo 16KB = 64KB.
// Epilogue stages h1 half2 via smem (reusing the A region) then coalesced STG.128.
#define GEMM_SMEM 65536
#define EPI_STRIDE 68

__device__ __forceinline__ void mma_bf16(float* c, uint4 a, uint2 b) {
    asm volatile(
        "mma.sync.aligned.m16n8k16.row.col.f32.bf16.bf16.f32 "
        "{%0,%1,%2,%3}, {%4,%5,%6,%7}, {%8,%9}, {%0,%1,%2,%3};"
        : "+f"(c[0]), "+f"(c[1]), "+f"(c[2]), "+f"(c[3])
        : "r"(a.x), "r"(a.y), "r"(a.z), "r"(a.w), "r"(b.x), "r"(b.y));
}

__global__ __launch_bounds__(256, 3) void k_gemm1(const float* __restrict__ x,
                                                  const float* __restrict__ att_s,
                                                  const float* __restrict__ att_d) {
    extern __shared__ char smem[];
    unsigned* sB   = reinterpret_cast<unsigned*>(smem);            // 32KB
    unsigned* sAhi = reinterpret_cast<unsigned*>(smem + 32768);    // 16KB
    unsigned* sAlo = reinterpret_cast<unsigned*>(smem + 49152);    // 16KB
    const int tid = threadIdx.x;
    const int n0 = blockIdx.x * 64;

    // ---- stage B: coalesced copy of precomputed fragments (2048 uint4) ----
    {
        uint4* d4 = reinterpret_cast<uint4*>(sB);
        const uint4* s4 = reinterpret_cast<const uint4*>(g_Bhi32);
        for (int i = tid; i < 2048; i += 256) d4[i] = s4[i];
    }
    // ---- stage A (x rows -> bf16 hi/lo, fragment order), 64 rows ----
    for (int i = tid; i < 64 * 64; i += 256) {        // i = row*64 + kpair
        int row = i >> 6, kp = i & 63;
        int n = n0 + row;
        float2 v = make_float2(0.f, 0.f);
        if (n < NN) v = reinterpret_cast<const float2*>(x)[n * 64 + kp];
        __nv_bfloat16 hx = __float2bfloat16_rn(v.x);
        __nv_bfloat16 hy = __float2bfloat16_rn(v.y);
        __nv_bfloat16 lx = __float2bfloat16_rn(v.x - __bfloat162float(hx));
        __nv_bfloat16 ly = __float2bfloat16_rn(v.y - __bfloat162float(hy));
        __nv_bfloat162 hp = {hx, hy}, lp = {lx, ly};
        int mb = row >> 4, r = row & 15, g = r & 7, half = r >> 3;
        int ks = kp >> 3, kk = kp & 7;
        int tg = kk & 3, khalf = kk >> 2;
        int addr = ((mb * 8 + ks) * 32 + g * 4 + tg) * 4 + (khalf * 2 + half);
        sAhi[addr] = *reinterpret_cast<unsigned*>(&hp);
        sAlo[addr] = *reinterpret_cast<unsigned*>(&lp);
    }
    __syncthreads();

    // ---- mainloop: warp = (mb 0..3, jhalf 0..1); 2 passes x 8 ks x 8 jj ----
    const int wid = tid >> 5, lane = tid & 31;
    const int mb = wid & 3;
    const int jhalf = wid >> 2;
    const int jbase = jhalf * 8;
    float c[8][4];
#pragma unroll
    for (int j = 0; j < 8; j++) {
        c[j][0] = 0.f; c[j][1] = 0.f; c[j][2] = 0.f; c[j][3] = 0.f;
    }
#pragma unroll 1
    for (int pass = 0; pass < 2; pass++) {
        const unsigned* sa = (pass == 0) ? sAhi : sAlo;
#pragma unroll
        for (int ks = 0; ks < 8; ks++) {
            uint4 af = *reinterpret_cast<const uint4*>(&sa[((mb * 8 + ks) * 32 + lane) * 4]);
#pragma unroll
            for (int jj = 0; jj < 8; jj++) {
                int j = jbase + jj;
                uint2 bf = *reinterpret_cast<const uint2*>(&sB[((j * 8 + ks) * 32 + lane) * 2]);
                mma_bf16(c[jj], af, bf);
            }
        }
    }

    // ---- epilogue part 1: attention scalars (registers + shfl only) ----
    const int g = lane >> 2, tg = lane & 3;
    const int rowA = mb * 16 + g;
    const int rowB = rowA + 8;
    const int nA = n0 + rowA, nB = n0 + rowB;
    float psA[2] = {0, 0}, pdA[2] = {0, 0};
    float psB[2] = {0, 0}, pdB[2] = {0, 0};
#pragma unroll
    for (int jj = 0; jj < 8; jj++) {
        int j = jbase + jj;
        int col0 = 8 * j + 2 * tg;
        float s0 = att_s[col0], s1 = att_s[col0 + 1];
        float d0 = att_d[col0], d1 = att_d[col0 + 1];
        int hloc = jj >> 2;
        psA[hloc] += c[jj][0] * s0 + c[jj][1] * s1;
        pdA[hloc] += c[jj][0] * d0 + c[jj][1] * d1;
        psB[hloc] += c[jj][2] * s0 + c[jj][3] * s1;
        pdB[hloc] += c[jj][2] * d0 + c[jj][3] * d1;
    }
#pragma unroll
    for (int h = 0; h < 2; h++) {
#pragma unroll
        for (int off = 2; off > 0; off >>= 1) {
            psA[h] += __shfl_down_sync(FULLM, psA[h], off, 4);
            pdA[h] += __shfl_down_sync(FULLM, pdA[h], off, 4);
            psB[h] += __shfl_down_sync(FULLM, psB[h], off, 4);
            pdB[h] += __shfl_down_sync(FULLM, pdB[h], off, 4);
        }
    }
    if (tg == 0) {
#pragma unroll
        for (int h = 0; h < 2; h++) {
            int head = 2 * jhalf + h;
            if (nA < NN) { g_asrc1[nA * 4 + head] = psA[h]; g_adst1[nA * 4 + head] = pdA[h]; }
            if (nB < NN) { g_asrc1[nB * 4 + head] = psB[h]; g_adst1[nB * 4 + head] = pdB[h]; }
        }
    }

    // ---- epilogue part 2: h1 through smem (conflict-free STS, coalesced STG.128) ----
    __syncthreads();           // mainloop smem reads done; reuse A region for staging
    unsigned* sh = reinterpret_cast<unsigned*>(smem + 32768);   // [64 rows][EPI_STRIDE]
#pragma unroll
    for (int jj = 0; jj < 8; jj++) {
        int j = jbase + jj;
        __half2 pA = __floats2half2_rn(c[jj][0], c[jj][1]);
        __half2 pB = __floats2half2_rn(c[jj][2], c[jj][3]);
        sh[rowA * EPI_STRIDE + 4 * j + tg] = *reinterpret_cast<unsigned*>(&pA);
        sh[rowB * EPI_STRIDE + 4 * j + tg] = *reinterpret_cast<unsigned*>(&pB);
    }
    __syncthreads();
    {
        uint4* h1u4 = reinterpret_cast<uint4*>(g_h1);
        for (int i = tid; i < 1024; i += 256) {       // 64 rows x 16 uint4
            int row = i >> 4, q = i & 15;
            int n = n0 + row;
            if (n < NN) {
                uint4 v = *reinterpret_cast<const uint4*>(&sh[row * EPI_STRIDE + 4 * q]);
                h1u4[n * 16 + q] = v;
            }
        }
    }
}

// ---------------- fused layer 1: softmax + aggregate + ELU + W2 proj ----------------
// one warp per destination node; fp16 h1 gathers (8B/lane/edge), unroll-8
__global__ __launch_bounds__(256) void k_layer1(const float* __restrict__ b1,
                                                const float* __restrict__ W2,
                                                const float* __restrict__ att_s2,
                                                const float* __restrict__ att_d2) {
    __shared__ int   ssrc[256];
    __shared__ float sex[256 * 4];
    int gt = blockIdx.x * blockDim.x + threadIdx.x;
    int n = gt >> 5;
    if (n >= NN) return;
    const int lane = gt & 31;
    const int head = lane >> 3;
    const int wslot = (threadIdx.x >> 5) * 32;

    const int beg = g_rowstart[n];
    const int end = beg + g_deg[n];
    const float4 adn = reinterpret_cast<const float4*>(g_adst1)[n];
    const uint2* __restrict__ h1v = g_h1;

    float acc0 = 0.0f, acc1 = 0.0f, acc2 = 0.0f, acc3 = 0.0f;
    float dx = 0.0f, dy = 0.0f, dz = 0.0f, dw = 0.0f;

    for (int c = beg; c < end; c += 32) {
        const int idx = c + lane;
        const int cnt = min(32, end - c);
        const int cnt8 = (cnt + 7) & ~7;
        __syncwarp(FULLM);
        {
            int s = g_csrc[min(idx, end - 1)];
            float4 as_ = reinterpret_cast<const float4*>(g_asrc1)[s];
            float v0 = as_.x + adn.x, v1 = as_.y + adn.y;
            float v2 = as_.z + adn.z, v3 = as_.w + adn.w;
            v0 = (v0 > 0.0f) ? v0 : NEG_SLOPE * v0;
            v1 = (v1 > 0.0f) ? v1 : NEG_SLOPE * v1;
            v2 = (v2 > 0.0f) ? v2 : NEG_SLOPE * v2;
            v3 = (v3 > 0.0f) ? v3 : NEG_SLOPE * v3;
            float e0 = expf(v0), e1 = expf(v1), e2 = expf(v2), e3 = expf(v3);
            if (idx >= end) { e0 = e1 = e2 = e3 = 0.0f; }
            dx += e0; dy += e1; dz += e2; dw += e3;
            ssrc[wslot + lane] = s;
            float* p = &sex[(wslot + lane) * 4];
            p[0] = e0; p[1] = e1; p[2] = e2; p[3] = e3;
        }
        __syncwarp(FULLM);
        for (int j = 0; j < cnt8; j += 8) {
            uint2 u[8];
#pragma unroll
            for (int i = 0; i < 8; i++) {
                int s = ssrc[wslot + j + i];
                u[i] = h1v[s * 32 + lane];
            }
#pragma unroll
            for (int i = 0; i < 8; i++) {
                float ex = sex[(wslot + j + i) * 4 + head];
                float2 a = __half22float2(*reinterpret_cast<__half2*>(&u[i].x));
                float2 b = __half22float2(*reinterpret_cast<__half2*>(&u[i].y));
                acc0 = fmaf(ex, a.x, acc0);
                acc1 = fmaf(ex, a.y, acc1);
                acc2 = fmaf(ex, b.x, acc2);
                acc3 = fmaf(ex, b.y, acc3);
            }
        }
    }
#pragma unroll
    for (int off = 16; off > 0; off >>= 1) {
        dx += __shfl_xor_sync(FULLM, dx, off);
        dy += __shfl_xor_sync(FULLM, dy, off);
        dz += __shfl_xor_sync(FULLM, dz, off);
        dw += __shfl_xor_sync(FULLM, dw, off);
    }
    float denh = (head == 0) ? dx : (head == 1) ? dy : (head == 2) ? dz : dw;
    float r = 1.0f / (denh + EPS_DEN);

    float av[4] = {acc0, acc1, acc2, acc3};
    float p0 = 0.0f, p1 = 0.0f;
#pragma unroll
    for (int m = 0; m < 4; m++) {
        int k = 4 * lane + m;
        float v = av[m] * r + b1[k];
        float ev = (v > 0.0f) ? v : expm1f(v);   // ELU
        p0 = fmaf(ev, W2[k * 2 + 0], p0);
        p1 = fmaf(ev, W2[k * 2 + 1], p1);
    }
#pragma unroll
    for (int off = 16; off > 0; off >>= 1) {
        p0 += __shfl_down_sync(FULLM, p0, off);
        p1 += __shfl_down_sync(FULLM, p1, off);
    }
    if (lane == 0) {
        g_h2[n * 2 + 0] = p0;
        g_h2[n * 2 + 1] = p1;
        g_asrc2[n] = p0 * att_s2[0] + p1 * att_s2[1];
        g_adst2[n] = p0 * att_d2[0] + p1 * att_d2[1];
    }
}

// ---------------- fused layer 2: softmax + aggregate + log_softmax ----------------
__global__ __launch_bounds__(256) void k_layer2(const float* __restrict__ b2,
                                                float* __restrict__ out) {
    int gt = blockIdx.x * blockDim.x + threadIdx.x;
    int n = gt >> 3;
    if (n >= NN) return;
    const int lane = gt & 7;

    const int beg = g_rowstart[n];
    const int end = beg + g_deg[n];
    const float adn = g_adst2[n];

    float den = 0.0f, o0 = 0.0f, o1 = 0.0f;
    for (int idx = beg + lane; idx < end; idx += 8) {
        int s = g_csrc[idx];
        float v = g_asrc2[s] + adn;
        v = (v > 0.0f) ? v : NEG_SLOPE * v;
        float ex = expf(v);
        float2 h = reinterpret_cast<const float2*>(g_h2)[s];
        den += ex;
        o0 = fmaf(ex, h.x, o0);
        o1 = fmaf(ex, h.y, o1);
    }
#pragma unroll
    for (int off = 4; off > 0; off >>= 1) {
        den += __shfl_down_sync(FULLM, den, off, 8);
        o0  += __shfl_down_sync(FULLM, o0, off, 8);
        o1  += __shfl_down_sync(FULLM, o1, off, 8);
    }
    if (lane == 0) {
        float r = 1.0f / (den + EPS_DEN);
        float a = o0 * r + b2[0];
        float b = o1 * r + b2[1];
        float m = fmaxf(a, b);
        float l = m + logf(expf(a - m) + expf(b - m));
        out[n * 2 + 0] = a - l;
        out[n * 2 + 1] = b - l;
    }
}

// ---------------- launch ----------------
extern "C" void kernel_launch(void* const* d_in, const int* in_sizes, int n_in,
                              void* d_out, int out_size) {
    const float* x    = (const float*)d_in[0];
    const int*   ei   = (const int*)d_in[1];
    const float* W1   = (const float*)d_in[2];
    const float* as1  = (const float*)d_in[3];
    const float* ad1  = (const float*)d_in[4];
    const float* b1   = (const float*)d_in[5];
    const float* W2   = (const float*)d_in[6];
    const float* as2  = (const float*)d_in[7];
    const float* ad2  = (const float*)d_in[8];
    const float* b2   = (const float*)d_in[9];
    float* out = (float*)d_out;

    (void)in_sizes; (void)n_in; (void)out_size;

    static cudaStream_t s_side = nullptr;
    static cudaEvent_t  s_evFork = nullptr, s_evJoin = nullptr;
    static void *p_deg = nullptr, *p_total = nullptr;
    if (s_side == nullptr) {
        cudaStreamCreateWithFlags(&s_side, cudaStreamNonBlocking);
        cudaEventCreateWithFlags(&s_evFork, cudaEventDisableTiming);
        cudaEventCreateWithFlags(&s_evJoin, cudaEventDisableTiming);
        cudaGetSymbolAddress(&p_deg, g_deg);
        cudaGetSymbolAddress(&p_total, g_total);
        cudaFuncSetAttribute(k_gemm1, cudaFuncAttributeMaxDynamicSharedMemorySize, GEMM_SMEM);
    }

    // fork: CSR build on side stream, prepB+gemm1 on main (disjoint state).
    // API-call order keeps k_gemm1 at capture node #6 for ncu (-s 5 -c 1).
    cudaEventRecord(s_evFork, 0);
    cudaStreamWaitEvent(s_side, s_evFork, 0);

    cudaMemsetAsync(p_deg, 0, NN * sizeof(int), s_side);         // 1
    cudaMemsetAsync(p_total, 0, sizeof(int), s_side);            // 2
    k_count<<<(EE / 8 + 255) / 256, 256, 0, s_side>>>(ei);       // 3
    k_offsets<<<(NN + 255) / 256, 256, 0, s_side>>>();           // 4

    k_prepB<<<32, 256>>>(W1);                                    // 5 (main)
    k_gemm1<<<(NN + 63) / 64, 256, GEMM_SMEM>>>(x, as1, ad1);    // 6 (main) <- profiled

    k_scatter<<<(EE / 8 + NN + 255) / 256, 256, 0, s_side>>>(ei); // 7 (side)
    cudaEventRecord(s_evJoin, s_side);

    // join: layer kernels need both CSR and gemm outputs
    cudaStreamWaitEvent(0, s_evJoin, 0);

    {
        long long tot = (long long)NN * 32;
        k_layer1<<<(int)((tot + 255) / 256), 256>>>(b1, W2, as2, ad2);  // 8
    }
    {
        long long tot = (long long)NN * 8;
        k_layer2<<<(int)((tot + 255) / 256), 256>>>(b2, out);           // 9
    }
}